// round 13
// baseline (speedup 1.0000x reference)
#include <cuda_runtime.h>
#include <cuda_bf16.h>

// L, R: [N, C, H, W] fp32 ; out: [N, C, D, H, W] fp32
// out[n,c,d,h,w] = (w >= d) ? L[n,c,h,w] - R[n,c,h,w-d] : 1.0f
//
// R13: depth-1 software-pipelined window loads — next chunk's R window is
// issued before the current chunk's stores, removing mid-stream L2-latency
// exposure from the store stream.
static constexpr int Nn = 2;
static constexpr int Cc = 32;
static constexpr int Hh = 128;
static constexpr int Ww = 256;
static constexpr int Dd = 48;

static constexpr int W4   = Ww / 4;        // 64 float4 per row
static constexpr int NCH  = Nn * Cc * Hh;  // 8192 rows
static constexpr int HW   = Hh * Ww;
static constexpr int HW4  = HW / 4;        // float4 stride between d planes

static constexpr int DCHUNK  = 16;               // disparities per window
static constexpr int NCHUNKS = Dd / DCHUNK;      // 3
static constexpr int WINF4   = DCHUNK / 4 + 2;   // 6 float4 = 24 floats
static constexpr int WINSZ   = 4 * WINF4;        // 24
static constexpr int BASE    = 4 * (WINF4 - 2);  // 16

__device__ __forceinline__ void load_window(const float4* __restrict__ rrow4,
                                            int w4, int c, float* win)
{
    #pragma unroll
    for (int j = 0; j < WINF4; ++j) {
        int idx = w4 - (c >> 2) - (WINF4 - 2) + j;
        idx = idx < 0 ? 0 : idx;                 // clamp; masked by (w>=d)
        float4 v = __ldg(rrow4 + idx);
        win[4 * j + 0] = v.x;
        win[4 * j + 1] = v.y;
        win[4 * j + 2] = v.z;
        win[4 * j + 3] = v.w;
    }
}

__global__ __launch_bounds__(256)
void cost_volume_kernel(const float* __restrict__ L,
                        const float* __restrict__ R,
                        float* __restrict__ out)
{
    int tid = blockIdx.x * 256 + threadIdx.x;   // exact grid: NCH*W4 threads
    int w4  = tid & (W4 - 1);                   // 0..63
    int row = tid >> 6;                         // 0..8191
    int h   = row & (Hh - 1);
    int nc  = row >> 7;

    int w = w4 * 4;

    const float4* __restrict__ rrow4 =
        reinterpret_cast<const float4*>(R + (size_t)row * Ww);

    // L operand: one LDG.128, reused for all 48 disparities.
    float4 lv = __ldg(reinterpret_cast<const float4*>(L + (size_t)row * Ww) + w4);

    float4* outp = reinterpret_cast<float4*>(
        out + ((size_t)(nc * Dd) * Hh + h) * (size_t)Ww + w);

    // Prologue: window for chunk 0.
    float cur[WINSZ];
    load_window(rrow4, w4, 0, cur);

    #pragma unroll
    for (int ci = 0; ci < NCHUNKS; ++ci) {
        const int c = ci * DCHUNK;

        // Prefetch next chunk's window BEFORE this chunk's stores, so the
        // L2 read latency overlaps the store burst instead of preceding it.
        float nxt[WINSZ];
        if (ci + 1 < NCHUNKS)
            load_window(rrow4, w4, c + DCHUNK, nxt);

        // Element r[w+k-d] (d = c+dd) lives at cur[BASE + k - dd]; indices
        // are compile-time constants after unrolling -> stays in registers.
        #pragma unroll
        for (int dd = 0; dd < DCHUNK; ++dd) {
            const int d = c + dd;
            float4 o;
            o.x = (w + 0 >= d) ? (lv.x - cur[BASE + 0 - dd]) : 1.0f;
            o.y = (w + 1 >= d) ? (lv.y - cur[BASE + 1 - dd]) : 1.0f;
            o.z = (w + 2 >= d) ? (lv.z - cur[BASE + 2 - dd]) : 1.0f;
            o.w = (w + 3 >= d) ? (lv.w - cur[BASE + 3 - dd]) : 1.0f;
            // Streaming store: evict-first in L2 (zero-reuse output stream).
            __stcs(outp + (size_t)d * HW4, o);
        }

        if (ci + 1 < NCHUNKS) {
            #pragma unroll
            for (int j = 0; j < WINSZ; ++j)
                cur[j] = nxt[j];                // register renames after unroll
        }
    }
}

extern "C" void kernel_launch(void* const* d_in, const int* in_sizes, int n_in,
                              void* d_out, int out_size)
{
    const float* L = (const float*)d_in[0];
    const float* R = (const float*)d_in[1];
    float* out = (float*)d_out;

    const int total_threads = NCH * W4;       // 524,288
    const int block = 256;
    const int grid  = total_threads / block;  // 2048
    cost_volume_kernel<<<grid, block>>>(L, R, out);
}

// round 14
// speedup vs baseline: 1.0201x; 1.0201x over previous
#include <cuda_runtime.h>
#include <cuda_bf16.h>

// L, R: [N, C, H, W] fp32 ; out: [N, C, D, H, W] fp32
// out[n,c,d,h,w] = (w >= d) ? L[n,c,h,w] - R[n,c,h,w-d] : 1.0f
//
// Champion config (R10) with BLOCK=128: finer CTA scheduling granularity,
// identical inner body. HBM-write-roofline bound.
static constexpr int Nn = 2;
static constexpr int Cc = 32;
static constexpr int Hh = 128;
static constexpr int Ww = 256;
static constexpr int Dd = 48;

static constexpr int W4   = Ww / 4;        // 64 float4 per row
static constexpr int NCH  = Nn * Cc * Hh;  // 8192 rows
static constexpr int HW   = Hh * Ww;
static constexpr int HW4  = HW / 4;        // float4 stride between d planes

static constexpr int BLOCK = 128;

static constexpr int DCHUNK = 24;              // disparities per register window
static constexpr int WINF4  = DCHUNK / 4 + 2;  // 8 float4 = 32 floats

__global__ __launch_bounds__(BLOCK)
void cost_volume_kernel(const float* __restrict__ L,
                        const float* __restrict__ R,
                        float* __restrict__ out)
{
    int tid = blockIdx.x * BLOCK + threadIdx.x; // exact grid: NCH*W4 threads
    int w4  = tid & (W4 - 1);                   // 0..63
    int row = tid >> 6;                         // 0..8191
    int h   = row & (Hh - 1);
    int nc  = row >> 7;

    int w = w4 * 4;

    const float4* __restrict__ rrow4 =
        reinterpret_cast<const float4*>(R + (size_t)row * Ww);

    // L operand: one LDG.128, reused for all 48 disparities.
    float4 lv = __ldg(reinterpret_cast<const float4*>(L + (size_t)row * Ww) + w4);

    float4* outp = reinterpret_cast<float4*>(
        out + ((size_t)(nc * Dd) * Hh + h) * (size_t)Ww + w);

    #pragma unroll
    for (int c = 0; c < Dd; c += DCHUNK) {
        // Register window over r[w-c-(DCHUNK-4) .. w-c+7] : WINF4 aligned
        // float4 loads (L2-resident). Addresses clamped to row start; clamped
        // garbage is masked to 1.0 by the (w>=d) predicate.
        float win[4 * WINF4];
        #pragma unroll
        for (int j = 0; j < WINF4; ++j) {
            int idx = w4 - (c >> 2) - (WINF4 - 2) + j;
            idx = idx < 0 ? 0 : idx;
            float4 v = __ldg(rrow4 + idx);
            win[4 * j + 0] = v.x;
            win[4 * j + 1] = v.y;
            win[4 * j + 2] = v.z;
            win[4 * j + 3] = v.w;
        }

        // Element r[w+k-d] (d = c+dd) lives at win[BASE + k - dd]; indices
        // are compile-time constants after unrolling -> window stays in regs.
        constexpr int BASE = 4 * (WINF4 - 2);

        #pragma unroll
        for (int dd = 0; dd < DCHUNK; ++dd) {
            const int d = c + dd;
            float4 o;
            o.x = (w + 0 >= d) ? (lv.x - win[BASE + 0 - dd]) : 1.0f;
            o.y = (w + 1 >= d) ? (lv.y - win[BASE + 1 - dd]) : 1.0f;
            o.z = (w + 2 >= d) ? (lv.z - win[BASE + 2 - dd]) : 1.0f;
            o.w = (w + 3 >= d) ? (lv.w - win[BASE + 3 - dd]) : 1.0f;
            // Streaming store: evict-first in L2 (zero-reuse output stream).
            __stcs(outp + (size_t)d * HW4, o);
        }
    }
}

extern "C" void kernel_launch(void* const* d_in, const int* in_sizes, int n_in,
                              void* d_out, int out_size)
{
    const float* L = (const float*)d_in[0];
    const float* R = (const float*)d_in[1];
    float* out = (float*)d_out;

    const int total_threads = NCH * W4;       // 524,288
    const int grid  = total_threads / BLOCK;  // 4096
    cost_volume_kernel<<<grid, BLOCK>>>(L, R, out);
}